// round 1
// baseline (speedup 1.0000x reference)
#include <cuda_runtime.h>
#include <mma.h>
#include <math.h>

using namespace nvcuda;

// Problem constants
#define NROWS 8192
#define DDIM  4096          // D_IN == D_OUT == 4096
#define ALPHA 0.2f

// GEMM tiling
#define BM 128
#define BN 128
#define BKT 16

// ---------------------------------------------------------------------------
// Scratch (device globals: no runtime allocation allowed)
// ---------------------------------------------------------------------------
__device__ float g_h[(size_t)NROWS * DDIM];     // h = x @ W^T   (134 MB)
__device__ float g_s1[NROWS];
__device__ float g_s2[NROWS];
__device__ float g_F1p[NROWS];   // exp(s1[i] - M_i)
__device__ float g_F1n[NROWS];   // exp(0.2*s1[i] - M_i)
__device__ float g_E2p[NROWS];   // exp(s2[j])
__device__ float g_E2n[NROWS];   // exp(0.2*s2[j])
__device__ float g_Zinv[NROWS];  // 1 / softmax denominator
__device__ float g_m2;           // max_j s2[j]

// ---------------------------------------------------------------------------
// GEMM1: g_h[8192,4096] = X[8192,4096] @ W[4096,4096]^T   (tf32 wmma)
// ---------------------------------------------------------------------------
__global__ __launch_bounds__(256) void gemm1_kernel(const float* __restrict__ X,
                                                    const float* __restrict__ W) {
    __shared__ float As[BM][BKT];   // As[i][k]
    __shared__ float Bs[BN][BKT];   // Bs[n][k] = W[colBase+n][k]  (col_major frag, ld=BKT)

    const int tid   = threadIdx.x;
    const int warp  = tid >> 5;
    const int warpM = warp >> 1;    // 0..3  -> 32 rows each
    const int warpN = warp & 1;     // 0..1  -> 64 cols each
    const int rowBase = blockIdx.y * BM;
    const int colBase = blockIdx.x * BN;

    wmma::fragment<wmma::accumulator, 16, 16, 8, float> acc[2][4];
    #pragma unroll
    for (int i = 0; i < 2; i++)
        #pragma unroll
        for (int j = 0; j < 4; j++)
            wmma::fill_fragment(acc[i][j], 0.0f);

    const float* Ag = X + (size_t)rowBase * DDIM;
    const float* Bg = W + (size_t)colBase * DDIM;

    for (int k0 = 0; k0 < DDIM; k0 += BKT) {
        #pragma unroll
        for (int e = tid; e < BM * BKT; e += 256) {
            int r = e >> 4, c = e & 15;
            As[r][c] = wmma::__float_to_tf32(Ag[(size_t)r * DDIM + k0 + c]);
            Bs[r][c] = wmma::__float_to_tf32(Bg[(size_t)r * DDIM + k0 + c]);
        }
        __syncthreads();
        #pragma unroll
        for (int kk = 0; kk < BKT; kk += 8) {
            wmma::fragment<wmma::matrix_a, 16, 16, 8, wmma::precision::tf32, wmma::row_major> af[2];
            wmma::fragment<wmma::matrix_b, 16, 16, 8, wmma::precision::tf32, wmma::col_major> bf[4];
            #pragma unroll
            for (int i = 0; i < 2; i++)
                wmma::load_matrix_sync(af[i], &As[warpM * 32 + i * 16][kk], BKT);
            #pragma unroll
            for (int j = 0; j < 4; j++)
                wmma::load_matrix_sync(bf[j], &Bs[warpN * 64 + j * 16][kk], BKT);
            #pragma unroll
            for (int i = 0; i < 2; i++)
                #pragma unroll
                for (int j = 0; j < 4; j++)
                    wmma::mma_sync(acc[i][j], af[i], bf[j], acc[i][j]);
        }
        __syncthreads();
    }

    #pragma unroll
    for (int i = 0; i < 2; i++)
        #pragma unroll
        for (int j = 0; j < 4; j++) {
            float* outp = g_h + (size_t)(rowBase + warpM * 32 + i * 16) * DDIM
                              + colBase + warpN * 64 + j * 16;
            wmma::store_matrix_sync(outp, acc[i][j], DDIM, wmma::mem_row_major);
        }
}

// ---------------------------------------------------------------------------
// s1[i] = h[i,:] . a[0:D],  s2[i] = h[i,:] . a[D:2D]   (one block per row)
// ---------------------------------------------------------------------------
__global__ __launch_bounds__(256) void s12_kernel(const float* __restrict__ a) {
    __shared__ float r1[256];
    __shared__ float r2[256];
    const int i = blockIdx.x;
    const float* hr = g_h + (size_t)i * DDIM;
    float p1 = 0.f, p2 = 0.f;
    for (int k = threadIdx.x; k < DDIM; k += 256) {
        float hv = hr[k];
        p1 += hv * a[k];
        p2 += hv * a[DDIM + k];
    }
    r1[threadIdx.x] = p1;
    r2[threadIdx.x] = p2;
    __syncthreads();
    for (int s = 128; s > 0; s >>= 1) {
        if (threadIdx.x < s) {
            r1[threadIdx.x] += r1[threadIdx.x + s];
            r2[threadIdx.x] += r2[threadIdx.x + s];
        }
        __syncthreads();
    }
    if (threadIdx.x == 0) {
        g_s1[i] = r1[0];
        g_s2[i] = r2[0];
    }
}

// ---------------------------------------------------------------------------
// m2 = max_j s2[j]
// ---------------------------------------------------------------------------
__global__ __launch_bounds__(256) void maxs2_kernel() {
    __shared__ float sm[256];
    float m = -1e30f;
    for (int j = threadIdx.x; j < NROWS; j += 256)
        m = fmaxf(m, g_s2[j]);
    sm[threadIdx.x] = m;
    __syncthreads();
    for (int s = 128; s > 0; s >>= 1) {
        if (threadIdx.x < s)
            sm[threadIdx.x] = fmaxf(sm[threadIdx.x], sm[threadIdx.x + s]);
        __syncthreads();
    }
    if (threadIdx.x == 0) g_m2 = sm[0];
}

// ---------------------------------------------------------------------------
// Per-row / per-col softmax factor precompute.
// M_i = lrelu(s1[i] + m2) is the exact row max (lrelu monotone).
// P[i,j] = (s1[i]+s2[j] > 0) ? F1p[i]*E2p[j] : F1n[i]*E2n[j]
// ---------------------------------------------------------------------------
__global__ __launch_bounds__(256) void prep_kernel() {
    const int i = blockIdx.x * 256 + threadIdx.x;
    if (i >= NROWS) return;
    const float s1v = g_s1[i];
    const float s2v = g_s2[i];
    const float m2  = g_m2;
    const float t = s1v + m2;
    const float M = (t > 0.f) ? t : ALPHA * t;
    g_F1p[i] = expf(s1v - M);
    g_F1n[i] = expf(ALPHA * s1v - M);
    g_E2p[i] = expf(s2v);
    g_E2n[i] = expf(ALPHA * s2v);
}

// ---------------------------------------------------------------------------
// Z_i = sum_j P[i,j]  -> store reciprocal
// ---------------------------------------------------------------------------
__global__ __launch_bounds__(256) void zsum_kernel() {
    __shared__ float sm[256];
    const int i = blockIdx.x;
    const float f1p = g_F1p[i];
    const float f1n = g_F1n[i];
    const float thr = -g_s1[i];
    float z = 0.f;
    for (int j = threadIdx.x; j < NROWS; j += 256) {
        float s2v = g_s2[j];
        z += (s2v > thr) ? f1p * g_E2p[j] : f1n * g_E2n[j];
    }
    sm[threadIdx.x] = z;
    __syncthreads();
    for (int s = 128; s > 0; s >>= 1) {
        if (threadIdx.x < s) sm[threadIdx.x] += sm[threadIdx.x + s];
        __syncthreads();
    }
    if (threadIdx.x == 0) g_Zinv[i] = 1.0f / sm[0];
}

// ---------------------------------------------------------------------------
// GEMM2 (fused): out_unnorm[i,n] = sum_j P(i,j) * h[j,n]
// A-tile (P) is GENERATED in smem each k-iter from the per-row/per-col factors.
// ---------------------------------------------------------------------------
__global__ __launch_bounds__(256) void gemm2_kernel(float* __restrict__ out) {
    __shared__ float Ps[BM][BKT];    // Ps[i][k]
    __shared__ float Hs[BKT][BN];    // Hs[k][n]  (row_major frag, ld=BN)
    __shared__ float sF1p[BM];
    __shared__ float sF1n[BM];
    __shared__ float sThr[BM];

    const int tid   = threadIdx.x;
    const int warp  = tid >> 5;
    const int warpM = warp >> 1;
    const int warpN = warp & 1;
    const int rowBase = blockIdx.y * BM;
    const int colBase = blockIdx.x * BN;

    if (tid < BM) {
        int i = rowBase + tid;
        sF1p[tid] = g_F1p[i];
        sF1n[tid] = g_F1n[i];
        sThr[tid] = -g_s1[i];
    }
    __syncthreads();

    wmma::fragment<wmma::accumulator, 16, 16, 8, float> acc[2][4];
    #pragma unroll
    for (int i = 0; i < 2; i++)
        #pragma unroll
        for (int j = 0; j < 4; j++)
            wmma::fill_fragment(acc[i][j], 0.0f);

    for (int j0 = 0; j0 < NROWS; j0 += BKT) {
        // Generate P tile (the attention numerator) on the fly
        #pragma unroll
        for (int e = tid; e < BM * BKT; e += 256) {
            int r = e >> 4, c = e & 15;
            int j = j0 + c;
            float s2v = g_s2[j];
            float p = (s2v > sThr[r]) ? sF1p[r] * g_E2p[j] : sF1n[r] * g_E2n[j];
            Ps[r][c] = wmma::__float_to_tf32(p);
        }
        // Load H tile
        #pragma unroll
        for (int e = tid; e < BKT * BN; e += 256) {
            int k = e >> 7, n = e & 127;
            Hs[k][n] = wmma::__float_to_tf32(g_h[(size_t)(j0 + k) * DDIM + colBase + n]);
        }
        __syncthreads();
        #pragma unroll
        for (int kk = 0; kk < BKT; kk += 8) {
            wmma::fragment<wmma::matrix_a, 16, 16, 8, wmma::precision::tf32, wmma::row_major> af[2];
            wmma::fragment<wmma::matrix_b, 16, 16, 8, wmma::precision::tf32, wmma::row_major> bf[4];
            #pragma unroll
            for (int i = 0; i < 2; i++)
                wmma::load_matrix_sync(af[i], &Ps[warpM * 32 + i * 16][kk], BKT);
            #pragma unroll
            for (int j = 0; j < 4; j++)
                wmma::load_matrix_sync(bf[j], &Hs[kk][warpN * 64 + j * 16], BN);
            #pragma unroll
            for (int i = 0; i < 2; i++)
                #pragma unroll
                for (int j = 0; j < 4; j++)
                    wmma::mma_sync(acc[i][j], af[i], bf[j], acc[i][j]);
        }
        __syncthreads();
    }

    #pragma unroll
    for (int i = 0; i < 2; i++)
        #pragma unroll
        for (int j = 0; j < 4; j++) {
            float* outp = out + (size_t)(rowBase + warpM * 32 + i * 16) * DDIM
                              + colBase + warpN * 64 + j * 16;
            wmma::store_matrix_sync(outp, acc[i][j], DDIM, wmma::mem_row_major);
        }
}

// ---------------------------------------------------------------------------
// Normalize: out[i,n] *= 1/Z_i
// ---------------------------------------------------------------------------
__global__ __launch_bounds__(256) void norm_kernel(float* __restrict__ out) {
    size_t idx = (size_t)blockIdx.x * 256 + threadIdx.x;
    int i = (int)(idx >> 12);   // / 4096
    out[idx] *= g_Zinv[i];
}

// ---------------------------------------------------------------------------
// Launch
// ---------------------------------------------------------------------------
extern "C" void kernel_launch(void* const* d_in, const int* in_sizes, int n_in,
                              void* d_out, int out_size) {
    // Identify inputs by element count (defensive vs. ordering):
    // x: 8192*64*64 = 33554432, W: 4096*4096 = 16777216, a: 2*4096 = 8192
    const float* x = nullptr;
    const float* W = nullptr;
    const float* a = nullptr;
    for (int i = 0; i < n_in; i++) {
        if (in_sizes[i] == 33554432)      x = (const float*)d_in[i];
        else if (in_sizes[i] == 16777216) W = (const float*)d_in[i];
        else if (in_sizes[i] == 8192)     a = (const float*)d_in[i];
    }
    float* out = (float*)d_out;

    dim3 gemmGrid(DDIM / BN, NROWS / BM);   // (32, 64)

    gemm1_kernel<<<gemmGrid, 256>>>(x, W);
    s12_kernel<<<NROWS, 256>>>(a);
    maxs2_kernel<<<1, 256>>>();
    prep_kernel<<<NROWS / 256, 256>>>();
    zsum_kernel<<<NROWS, 256>>>();
    gemm2_kernel<<<gemmGrid, 256>>>(out);
    norm_kernel<<<(unsigned)(((size_t)NROWS * DDIM) / 256), 256>>>(out);
}

// round 3
// speedup vs baseline: 3.4925x; 3.4925x over previous
#include <cuda_runtime.h>
#include <math.h>
#include <stdint.h>

// ---------------------------------------------------------------------------
// Problem constants
// ---------------------------------------------------------------------------
#define NROWS 8192
#define DDIM  4096
#define ALPHA 0.2f

#define BM 128
#define BN 128
#define BK 32
#define NSTAGE 4

// smem word-strides (padded, conflict-free fragment access)
#define AW   36      // A tile row stride in words  (32 + 4 pad)
#define B1W  36      // GEMM1 B tile row stride
#define B2W  136     // GEMM2 B tile row stride (128 + 8 pad)

#define A_STAGE_W   (BM * AW)          // 4608 words = 18432 B
#define B1_STAGE_W  (BN * B1W)         // 4608 words
#define B2_STAGE_W  (BK * B2W)         // 4352 words = 17408 B
#define B_BASE_W    (NSTAGE * A_STAGE_W)   // 18432 words (73728 B)

#define SMEM1_BYTES ((NSTAGE * (A_STAGE_W + B1_STAGE_W)) * 4)   // 147456
#define SMEM2_BYTES ((NSTAGE * (A_STAGE_W + B2_STAGE_W)) * 4)   // 143360

// ---------------------------------------------------------------------------
// Scratch device globals (no runtime allocation allowed)
// ---------------------------------------------------------------------------
__device__ float g_Xr[(size_t)NROWS * DDIM];   // tf32-rounded X
__device__ float g_Wr[(size_t)DDIM * DDIM];    // tf32-rounded W
__device__ float g_h[(size_t)NROWS * DDIM];    // h (row-major, tf32-rounded)
__device__ float g_s1[NROWS];
__device__ float g_s2[NROWS];
__device__ float g_F1p[NROWS];
__device__ float g_F1n[NROWS];
__device__ float g_E2p[NROWS];
__device__ float g_E2n[NROWS];
__device__ float g_Zinv[NROWS];
__device__ float g_m2;

// ---------------------------------------------------------------------------
// Helpers
// ---------------------------------------------------------------------------
__device__ __forceinline__ uint32_t f2tf(float x) {
    uint32_t r;
    asm("cvt.rna.tf32.f32 %0, %1;" : "=r"(r) : "f"(x));
    return r;
}

#define CP16(smem_addr, gptr) \
    asm volatile("cp.async.cg.shared.global [%0], [%1], 16;" \
                 :: "r"(smem_addr), "l"(gptr) : "memory")
#define CP_COMMIT()  asm volatile("cp.async.commit_group;" ::: "memory")
#define CP_WAIT2()   asm volatile("cp.async.wait_group 2;" ::: "memory")

#define MMA_TF32(d, a, b) \
    asm volatile("mma.sync.aligned.m16n8k8.row.col.f32.tf32.tf32.f32 " \
        "{%0,%1,%2,%3}, {%4,%5,%6,%7}, {%8,%9}, {%0,%1,%2,%3};" \
        : "+f"((d)[0]), "+f"((d)[1]), "+f"((d)[2]), "+f"((d)[3]) \
        : "r"((a)[0]), "r"((a)[1]), "r"((a)[2]), "r"((a)[3]), \
          "r"((b)[0]), "r"((b)[1]))

// ---------------------------------------------------------------------------
// Elementwise tf32 rounding (X, W pre-pass)
// ---------------------------------------------------------------------------
__global__ __launch_bounds__(256) void round_kernel(const float4* __restrict__ src,
                                                    float4* __restrict__ dst, int n4) {
    for (int i = blockIdx.x * 256 + threadIdx.x; i < n4; i += gridDim.x * 256) {
        float4 v = src[i];
        float4 o;
        o.x = __uint_as_float(f2tf(v.x));
        o.y = __uint_as_float(f2tf(v.y));
        o.z = __uint_as_float(f2tf(v.z));
        o.w = __uint_as_float(f2tf(v.w));
        dst[i] = o;
    }
}

// ---------------------------------------------------------------------------
// GEMM1: g_h[i][n] = sum_k Xr[i][k] * Wr[n][k]   (tf32 mma.sync, cp.async x4)
// ---------------------------------------------------------------------------
__global__ __launch_bounds__(256, 1) void gemm1_kernel() {
    extern __shared__ uint32_t sm[];
    const int tid = threadIdx.x, lane = tid & 31, wid = tid >> 5;
    const int warpM = wid & 1, warpN = wid >> 1;
    const int g = lane >> 2, q = lane & 3;
    const int rowBase = blockIdx.y * BM;
    const int colBase = blockIdx.x * BN;
    const uint32_t sbase = (uint32_t)__cvta_generic_to_shared(sm);
    const float* __restrict__ A = g_Xr;
    const float* __restrict__ B = g_Wr;
    const int T = DDIM / BK;   // 128

    float acc[4][4][4];
    #pragma unroll
    for (int i = 0; i < 4; i++)
        #pragma unroll
        for (int j = 0; j < 4; j++)
            #pragma unroll
            for (int e = 0; e < 4; e++) acc[i][j][e] = 0.f;

    // stage load: 1024 16B chunks each for A and B, 4 per thread
    #define G1_ISSUE(t) do { \
        int st_ = (t) & (NSTAGE - 1); \
        uint32_t sA_ = sbase + st_ * (A_STAGE_W * 4); \
        uint32_t sB_ = sbase + B_BASE_W * 4 + st_ * (B1_STAGE_W * 4); \
        int k0_ = (t) * BK; \
        _Pragma("unroll") \
        for (int c_ = 0; c_ < 4; c_++) { \
            int ch_ = tid + c_ * 256; \
            int r_ = ch_ >> 3, c16_ = ch_ & 7; \
            CP16(sA_ + r_ * (AW * 4) + c16_ * 16, \
                 A + (size_t)(rowBase + r_) * DDIM + k0_ + c16_ * 4); \
            CP16(sB_ + r_ * (B1W * 4) + c16_ * 16, \
                 B + (size_t)(colBase + r_) * DDIM + k0_ + c16_ * 4); \
        } \
    } while (0)

    #pragma unroll
    for (int t = 0; t < NSTAGE - 1; t++) { G1_ISSUE(t); CP_COMMIT(); }

    for (int t = 0; t < T; t++) {
        CP_WAIT2();
        __syncthreads();
        int tn = t + NSTAGE - 1;
        if (tn < T) G1_ISSUE(tn);
        CP_COMMIT();

        const uint32_t* As = sm + (t & (NSTAGE - 1)) * A_STAGE_W;
        const uint32_t* Bs = sm + B_BASE_W + (t & (NSTAGE - 1)) * B1_STAGE_W;
        #pragma unroll
        for (int kk = 0; kk < 4; kk++) {
            uint32_t a[4][4], b[4][2];
            #pragma unroll
            for (int fm = 0; fm < 4; fm++) {
                int r0 = warpM * 64 + fm * 16 + g;
                a[fm][0] = As[r0 * AW + kk * 8 + q];
                a[fm][1] = As[(r0 + 8) * AW + kk * 8 + q];
                a[fm][2] = As[r0 * AW + kk * 8 + q + 4];
                a[fm][3] = As[(r0 + 8) * AW + kk * 8 + q + 4];
            }
            #pragma unroll
            for (int fn = 0; fn < 4; fn++) {
                int n0 = warpN * 32 + fn * 8 + g;
                b[fn][0] = Bs[n0 * B1W + kk * 8 + q];
                b[fn][1] = Bs[n0 * B1W + kk * 8 + q + 4];
            }
            #pragma unroll
            for (int fm = 0; fm < 4; fm++)
                #pragma unroll
                for (int fn = 0; fn < 4; fn++)
                    MMA_TF32(acc[fm][fn], a[fm], b[fn]);
        }
    }

    // Epilogue: store h (tf32-rounded), row-major
    #pragma unroll
    for (int fm = 0; fm < 4; fm++) {
        int row = rowBase + warpM * 64 + fm * 16 + g;
        #pragma unroll
        for (int fn = 0; fn < 4; fn++) {
            int col = colBase + warpN * 32 + fn * 8 + q * 2;
            uint2 v0 = { f2tf(acc[fm][fn][0]), f2tf(acc[fm][fn][1]) };
            uint2 v1 = { f2tf(acc[fm][fn][2]), f2tf(acc[fm][fn][3]) };
            *(uint2*)&g_h[(size_t)row * DDIM + col] = v0;
            *(uint2*)&g_h[(size_t)(row + 8) * DDIM + col] = v1;
        }
    }
    #undef G1_ISSUE
}

// ---------------------------------------------------------------------------
// s1/s2: one warp per row of h
// ---------------------------------------------------------------------------
__global__ __launch_bounds__(256) void s12_kernel(const float* __restrict__ a) {
    const int wid = threadIdx.x >> 5, lane = threadIdx.x & 31;
    const int i = blockIdx.x * 8 + wid;
    const float* hr = g_h + (size_t)i * DDIM;
    float s1 = 0.f, s2 = 0.f;
    #pragma unroll 4
    for (int kb = 0; kb < 32; kb++) {
        int idx = kb * 128 + lane * 4;
        float4 h4 = *(const float4*)&hr[idx];
        float4 a1 = *(const float4*)&a[idx];
        float4 a2 = *(const float4*)&a[DDIM + idx];
        s1 += h4.x * a1.x + h4.y * a1.y + h4.z * a1.z + h4.w * a1.w;
        s2 += h4.x * a2.x + h4.y * a2.y + h4.z * a2.z + h4.w * a2.w;
    }
    #pragma unroll
    for (int s = 16; s > 0; s >>= 1) {
        s1 += __shfl_xor_sync(0xffffffffu, s1, s);
        s2 += __shfl_xor_sync(0xffffffffu, s2, s);
    }
    if (lane == 0) { g_s1[i] = s1; g_s2[i] = s2; }
}

__global__ __launch_bounds__(256) void maxs2_kernel() {
    __shared__ float sm[256];
    float m = -1e30f;
    for (int j = threadIdx.x; j < NROWS; j += 256) m = fmaxf(m, g_s2[j]);
    sm[threadIdx.x] = m;
    __syncthreads();
    for (int s = 128; s > 0; s >>= 1) {
        if (threadIdx.x < s) sm[threadIdx.x] = fmaxf(sm[threadIdx.x], sm[threadIdx.x + s]);
        __syncthreads();
    }
    if (threadIdx.x == 0) g_m2 = sm[0];
}

__global__ __launch_bounds__(256) void prep_kernel() {
    const int i = blockIdx.x * 256 + threadIdx.x;
    if (i >= NROWS) return;
    const float s1v = g_s1[i], s2v = g_s2[i], m2 = g_m2;
    const float t = s1v + m2;
    const float M = (t > 0.f) ? t : ALPHA * t;
    g_F1p[i] = expf(s1v - M);
    g_F1n[i] = expf(ALPHA * s1v - M);
    g_E2p[i] = expf(s2v);
    g_E2n[i] = expf(ALPHA * s2v);
}

// Z_i: 32 rows/block, 8 j-lanes per row, smem-tiled
__global__ __launch_bounds__(256) void zsum_kernel() {
    __shared__ float s2c[1024], epc[1024], enc[1024];
    const int tid = threadIdx.x;
    const int r = tid >> 3, gl = tid & 7;
    const int i = blockIdx.x * 32 + r;
    const float thr = -g_s1[i];
    float zp = 0.f, zn = 0.f;
    for (int c0 = 0; c0 < NROWS; c0 += 1024) {
        for (int k = tid; k < 1024; k += 256) {
            s2c[k] = g_s2[c0 + k];
            epc[k] = g_E2p[c0 + k];
            enc[k] = g_E2n[c0 + k];
        }
        __syncthreads();
        #pragma unroll 4
        for (int kk = 0; kk < 128; kk++) {
            int k = kk * 8 + gl;
            if (s2c[k] > thr) zp += epc[k]; else zn += enc[k];
        }
        __syncthreads();
    }
    float z = g_F1p[i] * zp + g_F1n[i] * zn;
    z += __shfl_down_sync(0xffffffffu, z, 4, 8);
    z += __shfl_down_sync(0xffffffffu, z, 2, 8);
    z += __shfl_down_sync(0xffffffffu, z, 1, 8);
    if (gl == 0) g_Zinv[i] = 1.0f / z;
}

// ---------------------------------------------------------------------------
// GEMM2: out[i][n] = Zinv[i] * sum_j P(i,j) * h[j][n]
// P generated into smem inside the pipeline; B = h tiles via cp.async.
// ---------------------------------------------------------------------------
__global__ __launch_bounds__(256, 1) void gemm2_kernel(float* __restrict__ out) {
    extern __shared__ uint32_t sm[];
    __shared__ float sF1p[BM], sF1n[BM], sThr[BM];
    const int tid = threadIdx.x, lane = tid & 31, wid = tid >> 5;
    const int warpM = wid & 1, warpN = wid >> 1;
    const int g = lane >> 2, q = lane & 3;
    const int rowBase = blockIdx.y * BM;
    const int colBase = blockIdx.x * BN;
    const uint32_t sbase = (uint32_t)__cvta_generic_to_shared(sm);
    const float* __restrict__ H = g_h;
    const int T = NROWS / BK;   // 256

    if (tid < BM) {
        int i = rowBase + tid;
        sF1p[tid] = g_F1p[i];
        sF1n[tid] = g_F1n[i];
        sThr[tid] = -g_s1[i];
    }
    __syncthreads();

    // P-gen assignment: 2 threads per row, 16 j each
    const int prow = tid >> 1, pjh = tid & 1;
    const float f1p = sF1p[prow], f1n = sF1n[prow], pthr = sThr[prow];
    char* smc = (char*)sm;

    float acc[4][4][4];
    #pragma unroll
    for (int i = 0; i < 4; i++)
        #pragma unroll
        for (int j = 0; j < 4; j++)
            #pragma unroll
            for (int e = 0; e < 4; e++) acc[i][j][e] = 0.f;

    #define G2_ISSUE(t) do { \
        int st_ = (t) & (NSTAGE - 1); \
        uint32_t sB_ = sbase + B_BASE_W * 4 + st_ * (B2_STAGE_W * 4); \
        int j0_ = (t) * BK; \
        _Pragma("unroll") \
        for (int c_ = 0; c_ < 4; c_++) { \
            int ch_ = tid + c_ * 256; \
            int r_ = ch_ >> 5, c16_ = ch_ & 31; \
            CP16(sB_ + r_ * (B2W * 4) + c16_ * 16, \
                 H + (size_t)(j0_ + r_) * DDIM + colBase + c16_ * 4); \
        } \
    } while (0)

    #define G2_PGEN(t) do { \
        int st_ = (t) & (NSTAGE - 1); \
        char* sA_ = smc + st_ * (A_STAGE_W * 4) + prow * (AW * 4) + pjh * 64; \
        int j0_ = (t) * BK + pjh * 16; \
        _Pragma("unroll") \
        for (int c_ = 0; c_ < 4; c_++) { \
            int j_ = j0_ + c_ * 4; \
            float4 s2v = *(const float4*)&g_s2[j_]; \
            float4 ep  = *(const float4*)&g_E2p[j_]; \
            float4 en  = *(const float4*)&g_E2n[j_]; \
            uint4 pv; \
            pv.x = f2tf((s2v.x > pthr) ? f1p * ep.x : f1n * en.x); \
            pv.y = f2tf((s2v.y > pthr) ? f1p * ep.y : f1n * en.y); \
            pv.z = f2tf((s2v.z > pthr) ? f1p * ep.z : f1n * en.z); \
            pv.w = f2tf((s2v.w > pthr) ? f1p * ep.w : f1n * en.w); \
            *(uint4*)(sA_ + c_ * 16) = pv; \
        } \
    } while (0)

    #pragma unroll
    for (int t = 0; t < NSTAGE - 1; t++) {
        G2_ISSUE(t);
        CP_COMMIT();
        G2_PGEN(t);
    }

    for (int t = 0; t < T; t++) {
        CP_WAIT2();
        __syncthreads();
        int tn = t + NSTAGE - 1;
        if (tn < T) G2_ISSUE(tn);
        CP_COMMIT();

        const uint32_t* As = sm + (t & (NSTAGE - 1)) * A_STAGE_W;
        const uint32_t* Bs = sm + B_BASE_W + (t & (NSTAGE - 1)) * B2_STAGE_W;
        #pragma unroll
        for (int kk = 0; kk < 4; kk++) {
            uint32_t a[4][4], b[4][2];
            #pragma unroll
            for (int fm = 0; fm < 4; fm++) {
                int r0 = warpM * 64 + fm * 16 + g;
                a[fm][0] = As[r0 * AW + kk * 8 + q];
                a[fm][1] = As[(r0 + 8) * AW + kk * 8 + q];
                a[fm][2] = As[r0 * AW + kk * 8 + q + 4];
                a[fm][3] = As[(r0 + 8) * AW + kk * 8 + q + 4];
            }
            #pragma unroll
            for (int fn = 0; fn < 4; fn++) {
                int n0 = warpN * 32 + fn * 8 + g;
                b[fn][0] = Bs[(kk * 8 + q) * B2W + n0];
                b[fn][1] = Bs[(kk * 8 + q + 4) * B2W + n0];
            }
            #pragma unroll
            for (int fm = 0; fm < 4; fm++)
                #pragma unroll
                for (int fn = 0; fn < 4; fn++)
                    MMA_TF32(acc[fm][fn], a[fm], b[fn]);
        }

        if (tn < T) G2_PGEN(tn);
    }

    // Epilogue: scale by Zinv, store out
    #pragma unroll
    for (int fm = 0; fm < 4; fm++) {
        int row = rowBase + warpM * 64 + fm * 16 + g;
        float zi0 = g_Zinv[row];
        float zi1 = g_Zinv[row + 8];
        #pragma unroll
        for (int fn = 0; fn < 4; fn++) {
            int col = colBase + warpN * 32 + fn * 8 + q * 2;
            float2 v0 = { acc[fm][fn][0] * zi0, acc[fm][fn][1] * zi0 };
            float2 v1 = { acc[fm][fn][2] * zi1, acc[fm][fn][3] * zi1 };
            *(float2*)&out[(size_t)row * DDIM + col] = v0;
            *(float2*)&out[(size_t)(row + 8) * DDIM + col] = v1;
        }
    }
    #undef G2_ISSUE
    #undef G2_PGEN
}

// ---------------------------------------------------------------------------
// Host launch
// ---------------------------------------------------------------------------
extern "C" void kernel_launch(void* const* d_in, const int* in_sizes, int n_in,
                              void* d_out, int out_size) {
    const float* x = nullptr;
    const float* W = nullptr;
    const float* a = nullptr;
    for (int i = 0; i < n_in; i++) {
        if (in_sizes[i] == 33554432)      x = (const float*)d_in[i];
        else if (in_sizes[i] == 16777216) W = (const float*)d_in[i];
        else if (in_sizes[i] == 8192)     a = (const float*)d_in[i];
    }
    float* out = (float*)d_out;

    static bool attr_done = false;
    if (!attr_done) {
        cudaFuncSetAttribute(gemm1_kernel, cudaFuncAttributeMaxDynamicSharedMemorySize, SMEM1_BYTES);
        cudaFuncSetAttribute(gemm2_kernel, cudaFuncAttributeMaxDynamicSharedMemorySize, SMEM2_BYTES);
        attr_done = true;
    }

    void* xr_ptr; cudaGetSymbolAddress(&xr_ptr, g_Xr);
    void* wr_ptr; cudaGetSymbolAddress(&wr_ptr, g_Wr);

    round_kernel<<<2048, 256>>>((const float4*)x, (float4*)xr_ptr, (int)((size_t)NROWS * DDIM / 4));
    round_kernel<<<2048, 256>>>((const float4*)W, (float4*)wr_ptr, (int)((size_t)DDIM * DDIM / 4));

    dim3 grid(DDIM / BN, NROWS / BM);   // (32, 64)
    gemm1_kernel<<<grid, 256, SMEM1_BYTES>>>();
    s12_kernel<<<NROWS / 8, 256>>>(a);
    maxs2_kernel<<<1, 256>>>();
    prep_kernel<<<NROWS / 256, 256>>>();
    zsum_kernel<<<NROWS / 32, 256>>>();
    gemm2_kernel<<<grid, 256, SMEM2_BYTES>>>(out);
}

// round 4
// speedup vs baseline: 4.2215x; 1.2087x over previous
#include <cuda_runtime.h>
#include <math.h>
#include <stdint.h>

// ---------------------------------------------------------------------------
#define NROWS 8192
#define DDIM  4096
#define ALPHA 0.2f

#define BM 128
#define BN 256
#define BK 32
#define NST 3

#define A_ST 16384
#define B_ST 32768
#define A_OFF(s) ((s) * A_ST)
#define B_OFF(s) (NST * A_ST + (s) * B_ST)
#define SMEM_MAIN (NST * (A_ST + B_ST))   // 147456

#define KTOT 512     // DDIM/8
#define JTOT 1024    // NROWS/8

// ---------------------------------------------------------------------------
// Scratch globals: fragment-permuted layouts.
// Xp[R][K][lane] float4 = {X[16R+g][8K+q], X[16R+8+g][8K+q],
//                          X[16R+g][8K+q+4], X[16R+8+g][8K+q+4]}, lane=g*4+q
// Wp same over W rows (n).  hp[Nb][Jk][lane] float4 =
//   {h[8Jk+q][16Nb+g], h[8Jk+q][16Nb+8+g], h[8Jk+q+4][16Nb+g], h[8Jk+q+4][16Nb+8+g]}
// ---------------------------------------------------------------------------
__device__ float g_Xp[(size_t)NROWS * DDIM];
__device__ float g_Wp[(size_t)DDIM * DDIM];
__device__ float g_hp[(size_t)NROWS * DDIM];
__device__ float g_s1[NROWS];
__device__ float g_s2[NROWS];
__device__ float g_F1p[NROWS];
__device__ float g_F1n[NROWS];
__device__ float g_E2p[NROWS];
__device__ float g_E2n[NROWS];
__device__ float g_Zinv[NROWS];
__device__ float g_m2;

// ---------------------------------------------------------------------------
__device__ __forceinline__ uint32_t f2tf(float x) {
    uint32_t r;
    asm("cvt.rna.tf32.f32 %0, %1;" : "=r"(r) : "f"(x));
    return r;
}

#define CP16(smem_addr, gptr) \
    asm volatile("cp.async.cg.shared.global [%0], [%1], 16;" \
                 :: "r"(smem_addr), "l"(gptr) : "memory")
#define CP_COMMIT() asm volatile("cp.async.commit_group;" ::: "memory")
#define CP_WAIT1()  asm volatile("cp.async.wait_group 1;" ::: "memory")

#define MMA4(d, av, b0, b1) \
    asm volatile("mma.sync.aligned.m16n8k8.row.col.f32.tf32.tf32.f32 " \
        "{%0,%1,%2,%3}, {%4,%5,%6,%7}, {%8,%9}, {%0,%1,%2,%3};" \
        : "+f"((d)[0]), "+f"((d)[1]), "+f"((d)[2]), "+f"((d)[3]) \
        : "r"((av).x), "r"((av).y), "r"((av).z), "r"((av).w), \
          "r"(b0), "r"(b1))

// ---------------------------------------------------------------------------
// Permute + tf32-round: src row-major [nrows][4096] -> fragment layout
// ---------------------------------------------------------------------------
__global__ __launch_bounds__(256) void permute_kernel(const float* __restrict__ src,
                                                      float4* __restrict__ dst) {
    __shared__ float Ts[16 * 520];
    const int tid = threadIdx.x;
    const int R = blockIdx.y;
    const int bx = blockIdx.x;           // 512-col chunk
    #pragma unroll
    for (int c = 0; c < 8; c++) {
        int id = tid + 256 * c;
        int row = id >> 7, c4 = id & 127;
        float4 v = *(const float4*)&src[((size_t)(R * 16 + row)) * DDIM + bx * 512 + c4 * 4];
        *(float4*)&Ts[row * 520 + c4 * 4] = v;
    }
    __syncthreads();
    const int lane = tid & 31, g = lane >> 2, q = lane & 3;
    #pragma unroll
    for (int c = 0; c < 8; c++) {
        int id = tid + 256 * c;
        int l = id & 31, K_ = id >> 5;
        int gg = l >> 2, qq = l & 3;
        uint4 v;
        v.x = f2tf(Ts[gg * 520 + K_ * 8 + qq]);
        v.y = f2tf(Ts[(gg + 8) * 520 + K_ * 8 + qq]);
        v.z = f2tf(Ts[gg * 520 + K_ * 8 + qq + 4]);
        v.w = f2tf(Ts[(gg + 8) * 520 + K_ * 8 + qq + 4]);
        dst[((size_t)R * KTOT + bx * 64 + K_) * 32 + l] = *(float4*)&v;
    }
    (void)g; (void)q; (void)lane;
}

// ---------------------------------------------------------------------------
// GEMM1: h = X @ W^T, output written fragment-permuted (g_hp) + tf32-rounded
// ---------------------------------------------------------------------------
__global__ __launch_bounds__(256, 1) void gemm1_kernel() {
    extern __shared__ char smem[];
    const uint32_t sb = (uint32_t)__cvta_generic_to_shared(smem);
    const int tid = threadIdx.x, lane = tid & 31, wid = tid >> 5;
    const int warpM = wid & 1, warpN = wid >> 1;   // 2 x 4 warps, 64x64 tiles
    const int g = lane >> 2, q = lane & 3;
    const int rowBase = blockIdx.y * BM;
    const int colBase = blockIdx.x * BN;
    const int Rbase = rowBase >> 4, NbBase = colBase >> 4;
    const float4* Xp4 = (const float4*)g_Xp;
    const float4* Wp4 = (const float4*)g_Wp;
    const int T = DDIM / BK;   // 128

    float acc[4][8][4];
    #pragma unroll
    for (int i = 0; i < 4; i++)
        #pragma unroll
        for (int j = 0; j < 8; j++)
            #pragma unroll
            for (int e = 0; e < 4; e++) acc[i][j][e] = 0.f;

    #define G1_ISSUE(t) do { \
        int st_ = (t) % NST; \
        _Pragma("unroll") \
        for (int c_ = 0; c_ < 4; c_++) { \
            int id_ = tid + 256 * c_; \
            int l_ = id_ & 31, K_ = (id_ >> 5) & 3, R_ = id_ >> 7; \
            CP16(sb + A_OFF(st_) + id_ * 16, \
                 Xp4 + ((size_t)(Rbase + R_) * KTOT + (t) * 4 + K_) * 32 + l_); \
        } \
        _Pragma("unroll") \
        for (int c_ = 0; c_ < 8; c_++) { \
            int id_ = tid + 256 * c_; \
            int l_ = id_ & 31, K_ = (id_ >> 5) & 3, Nb_ = id_ >> 7; \
            CP16(sb + B_OFF(st_) + id_ * 16, \
                 Wp4 + ((size_t)(NbBase + Nb_) * KTOT + (t) * 4 + K_) * 32 + l_); \
        } \
    } while (0)

    G1_ISSUE(0); CP_COMMIT();
    G1_ISSUE(1); CP_COMMIT();

    for (int t = 0; t < T; t++) {
        CP_WAIT1();
        __syncthreads();
        if (t + 2 < T) G1_ISSUE(t + 2);
        CP_COMMIT();

        const int st = t % NST;
        const uint4* As = (const uint4*)(smem + A_OFF(st));
        const uint4* Bs = (const uint4*)(smem + B_OFF(st));
        #pragma unroll
        for (int kk = 0; kk < 4; kk++) {
            uint4 av[4], bv[4];
            #pragma unroll
            for (int fm = 0; fm < 4; fm++)
                av[fm] = As[((warpM * 4 + fm) * 4 + kk) * 32 + lane];
            #pragma unroll
            for (int p = 0; p < 4; p++)
                bv[p] = Bs[((warpN * 4 + p) * 4 + kk) * 32 + lane];
            #pragma unroll
            for (int fm = 0; fm < 4; fm++)
                #pragma unroll
                for (int p = 0; p < 4; p++) {
                    MMA4(acc[fm][2 * p],     av[fm], bv[p].x, bv[p].z);
                    MMA4(acc[fm][2 * p + 1], av[fm], bv[p].y, bv[p].w);
                }
        }
    }
    #undef G1_ISSUE

    // Epilogue: restage tile in smem, then fragment-permuted write to g_hp
    __syncthreads();
    float* Hs = (float*)smem;          // stride 264
    #pragma unroll
    for (int fm = 0; fm < 4; fm++) {
        int r = warpM * 64 + fm * 16 + g;
        #pragma unroll
        for (int fn = 0; fn < 8; fn++) {
            int c = warpN * 64 + fn * 8 + 2 * q;
            *(float2*)&Hs[r * 264 + c]       = *(float2*)&acc[fm][fn][0];
            *(float2*)&Hs[(r + 8) * 264 + c] = *(float2*)&acc[fm][fn][2];
        }
    }
    __syncthreads();
    float4* hp4 = (float4*)g_hp;
    const int JkBase = rowBase >> 3;
    #pragma unroll
    for (int p = 0; p < 32; p++) {
        int idx = wid * 32 + p;
        int Nb_ = idx >> 4, Jk_ = idx & 15;
        int r1 = Jk_ * 8 + q, n1 = Nb_ * 16 + g;
        uint4 v;
        v.x = f2tf(Hs[r1 * 264 + n1]);
        v.y = f2tf(Hs[r1 * 264 + n1 + 8]);
        v.z = f2tf(Hs[(r1 + 4) * 264 + n1]);
        v.w = f2tf(Hs[(r1 + 4) * 264 + n1 + 8]);
        hp4[((size_t)(NbBase + Nb_) * JTOT + JkBase + Jk_) * 32 + lane] = *(float4*)&v;
    }
}

// ---------------------------------------------------------------------------
// s1/s2 from permuted h
// ---------------------------------------------------------------------------
__global__ __launch_bounds__(256) void s12_kernel(const float* __restrict__ a) {
    __shared__ float sa1[DDIM];
    __shared__ float sa2[DDIM];
    const int tid = threadIdx.x, lane = tid & 31, wid = tid >> 5;
    const int g = lane >> 2, q = lane & 3;
    for (int k = tid; k < DDIM; k += 256) {
        sa1[k] = a[k];
        sa2[k] = a[DDIM + k];
    }
    __syncthreads();
    const int Jk = blockIdx.x * 8 + wid;
    const float4* hp4 = (const float4*)g_hp;
    float s1a = 0.f, s1b = 0.f, s2a = 0.f, s2b = 0.f;
    for (int Nb = 0; Nb < 256; Nb++) {
        float4 v = hp4[((size_t)Nb * JTOT + Jk) * 32 + lane];
        int n1 = Nb * 16 + g, n2 = n1 + 8;
        float a1x = sa1[n1], a1y = sa1[n2], a2x = sa2[n1], a2y = sa2[n2];
        s1a += v.x * a1x + v.y * a1y;
        s1b += v.z * a1x + v.w * a1y;
        s2a += v.x * a2x + v.y * a2y;
        s2b += v.z * a2x + v.w * a2y;
    }
    #pragma unroll
    for (int m = 16; m >= 4; m >>= 1) {
        s1a += __shfl_xor_sync(0xffffffffu, s1a, m);
        s1b += __shfl_xor_sync(0xffffffffu, s1b, m);
        s2a += __shfl_xor_sync(0xffffffffu, s2a, m);
        s2b += __shfl_xor_sync(0xffffffffu, s2b, m);
    }
    if (g == 0) {
        int i = Jk * 8 + q;
        g_s1[i] = s1a; g_s1[i + 4] = s1b;
        g_s2[i] = s2a; g_s2[i + 4] = s2b;
    }
}

__global__ __launch_bounds__(256) void maxs2_kernel() {
    __shared__ float sm[256];
    float m = -1e30f;
    for (int j = threadIdx.x; j < NROWS; j += 256) m = fmaxf(m, g_s2[j]);
    sm[threadIdx.x] = m;
    __syncthreads();
    for (int s = 128; s > 0; s >>= 1) {
        if (threadIdx.x < s) sm[threadIdx.x] = fmaxf(sm[threadIdx.x], sm[threadIdx.x + s]);
        __syncthreads();
    }
    if (threadIdx.x == 0) g_m2 = sm[0];
}

__global__ __launch_bounds__(256) void prep_kernel() {
    const int i = blockIdx.x * 256 + threadIdx.x;
    if (i >= NROWS) return;
    const float s1v = g_s1[i], s2v = g_s2[i], m2 = g_m2;
    const float t = s1v + m2;
    const float M = (t > 0.f) ? t : ALPHA * t;
    g_F1p[i] = expf(s1v - M);
    g_F1n[i] = expf(ALPHA * s1v - M);
    g_E2p[i] = expf(s2v);
    g_E2n[i] = expf(ALPHA * s2v);
}

__global__ __launch_bounds__(256) void zsum_kernel() {
    __shared__ float s2c[1024], epc[1024], enc[1024];
    const int tid = threadIdx.x;
    const int r = tid >> 3, gl = tid & 7;
    const int i = blockIdx.x * 32 + r;
    const float thr = -g_s1[i];
    float zp = 0.f, zn = 0.f;
    for (int c0 = 0; c0 < NROWS; c0 += 1024) {
        for (int k = tid; k < 1024; k += 256) {
            s2c[k] = g_s2[c0 + k];
            epc[k] = g_E2p[c0 + k];
            enc[k] = g_E2n[c0 + k];
        }
        __syncthreads();
        #pragma unroll 4
        for (int kk = 0; kk < 128; kk++) {
            int k = kk * 8 + gl;
            if (s2c[k] > thr) zp += epc[k]; else zn += enc[k];
        }
        __syncthreads();
    }
    float z = g_F1p[i] * zp + g_F1n[i] * zn;
    z += __shfl_down_sync(0xffffffffu, z, 4, 8);
    z += __shfl_down_sync(0xffffffffu, z, 2, 8);
    z += __shfl_down_sync(0xffffffffu, z, 1, 8);
    if (gl == 0) g_Zinv[i] = 1.0f / z;
}

// ---------------------------------------------------------------------------
// GEMM2: out[i][n] = Zinv[i] * sum_j P(i,j) h[j][n]; P generated in fragment
// layout via STS.128; B = g_hp tiles via cp.async.
// ---------------------------------------------------------------------------
__global__ __launch_bounds__(256, 1) void gemm2_kernel(float* __restrict__ out) {
    extern __shared__ char smem[];
    const uint32_t sb = (uint32_t)__cvta_generic_to_shared(smem);
    const int tid = threadIdx.x, lane = tid & 31, wid = tid >> 5;
    const int warpM = wid & 1, warpN = wid >> 1;
    const int g = lane >> 2, q = lane & 3;
    const int rowBase = blockIdx.y * BM;
    const int colBase = blockIdx.x * BN;
    const int NbBase = colBase >> 4;
    const float4* hp4 = (const float4*)g_hp;
    const int T = NROWS / BK;   // 256

    // P-gen row factors (rows 16*wid + g, + 8)
    const int i1 = rowBase + wid * 16 + g;
    const float f1p1 = g_F1p[i1], f1n1 = g_F1n[i1], th1 = -g_s1[i1];
    const float f1p2 = g_F1p[i1 + 8], f1n2 = g_F1n[i1 + 8], th2 = -g_s1[i1 + 8];

    float acc[4][8][4];
    #pragma unroll
    for (int i = 0; i < 4; i++)
        #pragma unroll
        for (int j = 0; j < 8; j++)
            #pragma unroll
            for (int e = 0; e < 4; e++) acc[i][j][e] = 0.f;

    #define G2_ISSUE(t) do { \
        int st_ = (t) % NST; \
        _Pragma("unroll") \
        for (int c_ = 0; c_ < 8; c_++) { \
            int id_ = tid + 256 * c_; \
            int l_ = id_ & 31, Jq_ = (id_ >> 5) & 3, Nb_ = id_ >> 7; \
            CP16(sb + B_OFF(st_) + id_ * 16, \
                 hp4 + ((size_t)(NbBase + Nb_) * JTOT + (t) * 4 + Jq_) * 32 + l_); \
        } \
    } while (0)

    #define G2_PGEN(t) do { \
        int st_ = (t) % NST; \
        _Pragma("unroll") \
        for (int kk_ = 0; kk_ < 4; kk_++) { \
            int j1_ = (t) * BK + kk_ * 8 + q; \
            float s2a_ = g_s2[j1_], s2b_ = g_s2[j1_ + 4]; \
            float epa_ = g_E2p[j1_], epb_ = g_E2p[j1_ + 4]; \
            float ena_ = g_E2n[j1_], enb_ = g_E2n[j1_ + 4]; \
            uint4 v_; \
            v_.x = f2tf((s2a_ > th1) ? f1p1 * epa_ : f1n1 * ena_); \
            v_.y = f2tf((s2a_ > th2) ? f1p2 * epa_ : f1n2 * ena_); \
            v_.z = f2tf((s2b_ > th1) ? f1p1 * epb_ : f1n1 * enb_); \
            v_.w = f2tf((s2b_ > th2) ? f1p2 * epb_ : f1n2 * enb_); \
            asm volatile("st.shared.v4.b32 [%0], {%1,%2,%3,%4};" \
                :: "r"(sb + A_OFF(st_) + ((wid * 4 + kk_) * 32 + lane) * 16), \
                   "r"(v_.x), "r"(v_.y), "r"(v_.z), "r"(v_.w) : "memory"); \
        } \
    } while (0)

    G2_ISSUE(0); CP_COMMIT();
    G2_ISSUE(1); CP_COMMIT();
    G2_PGEN(0);
    G2_PGEN(1);

    for (int t = 0; t < T; t++) {
        CP_WAIT1();
        __syncthreads();
        if (t + 2 < T) G2_ISSUE(t + 2);
        CP_COMMIT();

        const int st = t % NST;
        const uint4* As = (const uint4*)(smem + A_OFF(st));
        const uint4* Bs = (const uint4*)(smem + B_OFF(st));
        #pragma unroll
        for (int kk = 0; kk < 4; kk++) {
            uint4 av[4], bv[4];
            #pragma unroll
            for (int fm = 0; fm < 4; fm++)
                av[fm] = As[((warpM * 4 + fm) * 4 + kk) * 32 + lane];
            #pragma unroll
            for (int p = 0; p < 4; p++)
                bv[p] = Bs[((warpN * 4 + p) * 4 + kk) * 32 + lane];
            #pragma unroll
            for (int fm = 0; fm < 4; fm++)
                #pragma unroll
                for (int p = 0; p < 4; p++) {
                    MMA4(acc[fm][2 * p],     av[fm], bv[p].x, bv[p].z);
                    MMA4(acc[fm][2 * p + 1], av[fm], bv[p].y, bv[p].w);
                }
        }
        if (t + 1 < T) G2_PGEN(t + 1);
    }
    #undef G2_ISSUE
    #undef G2_PGEN

    // Epilogue: scale by Zinv, direct stores
    #pragma unroll
    for (int fm = 0; fm < 4; fm++) {
        int r = rowBase + warpM * 64 + fm * 16 + g;
        float zi1 = g_Zinv[r], zi2 = g_Zinv[r + 8];
        #pragma unroll
        for (int fn = 0; fn < 8; fn++) {
            int c = colBase + warpN * 64 + fn * 8 + 2 * q;
            float2 v0 = { acc[fm][fn][0] * zi1, acc[fm][fn][1] * zi1 };
            float2 v1 = { acc[fm][fn][2] * zi2, acc[fm][fn][3] * zi2 };
            *(float2*)&out[(size_t)r * DDIM + c] = v0;
            *(float2*)&out[(size_t)(r + 8) * DDIM + c] = v1;
        }
    }
}

// ---------------------------------------------------------------------------
extern "C" void kernel_launch(void* const* d_in, const int* in_sizes, int n_in,
                              void* d_out, int out_size) {
    const float* x = nullptr;
    const float* W = nullptr;
    const float* a = nullptr;
    for (int i = 0; i < n_in; i++) {
        if (in_sizes[i] == 33554432)      x = (const float*)d_in[i];
        else if (in_sizes[i] == 16777216) W = (const float*)d_in[i];
        else if (in_sizes[i] == 8192)     a = (const float*)d_in[i];
    }
    float* out = (float*)d_out;

    static bool attr_done = false;
    if (!attr_done) {
        cudaFuncSetAttribute(gemm1_kernel, cudaFuncAttributeMaxDynamicSharedMemorySize, SMEM_MAIN);
        cudaFuncSetAttribute(gemm2_kernel, cudaFuncAttributeMaxDynamicSharedMemorySize, SMEM_MAIN);
        attr_done = true;
    }

    void* xp; cudaGetSymbolAddress(&xp, g_Xp);
    void* wp; cudaGetSymbolAddress(&wp, g_Wp);

    permute_kernel<<<dim3(8, NROWS / 16), 256>>>(x, (float4*)xp);
    permute_kernel<<<dim3(8, DDIM / 16), 256>>>(W, (float4*)wp);

    dim3 grid(DDIM / BN, NROWS / BM);   // (16, 64)
    gemm1_kernel<<<grid, 256, SMEM_MAIN>>>();
    s12_kernel<<<JTOT / 8, 256>>>(a);
    maxs2_kernel<<<1, 256>>>();
    prep_kernel<<<NROWS / 256, 256>>>();
    zsum_kernel<<<NROWS / 32, 256>>>();
    gemm2_kernel<<<grid, 256, SMEM_MAIN>>>(out);
}

// round 5
// speedup vs baseline: 12.0044x; 2.8436x over previous
#include <cuda_runtime.h>
#include <math.h>
#include <stdint.h>

// ---------------------------------------------------------------------------
#define NROWS 8192
#define DDIM  4096
#define ALPHA 0.2f

#define BM 128
#define BN 256
#define BK 32
#define NST 3

#define A_ST 16384
#define B_ST 32768
#define A_OFF(s) ((s) * A_ST)
#define B_OFF(s) (NST * A_ST + (s) * B_ST)
#define SMEM_MAIN (NST * (A_ST + B_ST))   // 147456

#define KTOT 512     // DDIM/8
#define NCHUNK 64
#define CHROWS 128   // NROWS / NCHUNK

// ---------------------------------------------------------------------------
// Scratch globals
// ---------------------------------------------------------------------------
__device__ float g_Xp[(size_t)NROWS * DDIM];   // fragment-permuted X (tf32)
__device__ float g_Wp[(size_t)DDIM * DDIM];    // fragment-permuted W (tf32)
__device__ float g_h[(size_t)NROWS * DDIM];    // h row-major fp32
__device__ float g_s1[NROWS];
__device__ float g_s2[NROWS];
__device__ float g_F1p[NROWS];
__device__ float g_F1n[NROWS];
__device__ float g_E2p[NROWS];
__device__ float g_E2n[NROWS];
__device__ float g_m2;

// sorted-by-s2-desc structures
__device__ int   g_sIdx[NROWS];
__device__ float g_sS2[NROWS];
__device__ float g_sWp[NROWS];
__device__ float g_sWn[NROWS];
__device__ float g_psP[NROWS + 1];   // exclusive scalar prefix of sWp
__device__ float g_psN[NROWS + 1];
__device__ int   g_cut[NROWS];
__device__ float g_zinv[NROWS];

// chunk sums / prefixes and full vector prefix scan
__device__ float g_CSp[NCHUNK * DDIM];
__device__ float g_CSn[NCHUNK * DDIM];
__device__ float g_CPp[NCHUNK * DDIM];
__device__ float g_CPn[NCHUNK * DDIM];
__device__ float g_TOTn[DDIM];
__device__ float2 g_PS[(size_t)(NROWS + 1) * DDIM];   // 268 MB

// ---------------------------------------------------------------------------
__device__ __forceinline__ uint32_t f2tf(float x) {
    uint32_t r;
    asm("cvt.rna.tf32.f32 %0, %1;" : "=r"(r) : "f"(x));
    return r;
}

#define CP16(smem_addr, gptr) \
    asm volatile("cp.async.cg.shared.global [%0], [%1], 16;" \
                 :: "r"(smem_addr), "l"(gptr) : "memory")
#define CP_COMMIT() asm volatile("cp.async.commit_group;" ::: "memory")
#define CP_WAIT1()  asm volatile("cp.async.wait_group 1;" ::: "memory")

#define MMA4(d, av, b0, b1) \
    asm volatile("mma.sync.aligned.m16n8k8.row.col.f32.tf32.tf32.f32 " \
        "{%0,%1,%2,%3}, {%4,%5,%6,%7}, {%8,%9}, {%0,%1,%2,%3};" \
        : "+f"((d)[0]), "+f"((d)[1]), "+f"((d)[2]), "+f"((d)[3]) \
        : "r"((av).x), "r"((av).y), "r"((av).z), "r"((av).w), \
          "r"(b0), "r"(b1))

// ---------------------------------------------------------------------------
// Permute + tf32-round: src row-major [nrows][4096] -> fragment layout
// ---------------------------------------------------------------------------
__global__ __launch_bounds__(256) void permute_kernel(const float* __restrict__ src,
                                                      float4* __restrict__ dst) {
    __shared__ float Ts[16 * 520];
    const int tid = threadIdx.x;
    const int R = blockIdx.y;
    const int bx = blockIdx.x;
    #pragma unroll
    for (int c = 0; c < 8; c++) {
        int id = tid + 256 * c;
        int row = id >> 7, c4 = id & 127;
        float4 v = *(const float4*)&src[((size_t)(R * 16 + row)) * DDIM + bx * 512 + c4 * 4];
        *(float4*)&Ts[row * 520 + c4 * 4] = v;
    }
    __syncthreads();
    #pragma unroll
    for (int c = 0; c < 8; c++) {
        int id = tid + 256 * c;
        int l = id & 31, K_ = id >> 5;
        int gg = l >> 2, qq = l & 3;
        uint4 v;
        v.x = f2tf(Ts[gg * 520 + K_ * 8 + qq]);
        v.y = f2tf(Ts[(gg + 8) * 520 + K_ * 8 + qq]);
        v.z = f2tf(Ts[gg * 520 + K_ * 8 + qq + 4]);
        v.w = f2tf(Ts[(gg + 8) * 520 + K_ * 8 + qq + 4]);
        dst[((size_t)R * KTOT + bx * 64 + K_) * 32 + l] = *(float4*)&v;
    }
}

// ---------------------------------------------------------------------------
// GEMM1: h = X @ W^T  (tf32 mma.sync, fragment-permuted operands)
// ---------------------------------------------------------------------------
__global__ __launch_bounds__(256, 1) void gemm1_kernel() {
    extern __shared__ char smem[];
    const uint32_t sb = (uint32_t)__cvta_generic_to_shared(smem);
    const int tid = threadIdx.x, lane = tid & 31, wid = tid >> 5;
    const int warpM = wid & 1, warpN = wid >> 1;
    const int g = lane >> 2, q = lane & 3;
    const int rowBase = blockIdx.y * BM;
    const int colBase = blockIdx.x * BN;
    const int Rbase = rowBase >> 4, NbBase = colBase >> 4;
    const float4* Xp4 = (const float4*)g_Xp;
    const float4* Wp4 = (const float4*)g_Wp;
    const int T = DDIM / BK;   // 128

    float acc[4][8][4];
    #pragma unroll
    for (int i = 0; i < 4; i++)
        #pragma unroll
        for (int j = 0; j < 8; j++)
            #pragma unroll
            for (int e = 0; e < 4; e++) acc[i][j][e] = 0.f;

    #define G1_ISSUE(t) do { \
        int st_ = (t) % NST; \
        _Pragma("unroll") \
        for (int c_ = 0; c_ < 4; c_++) { \
            int id_ = tid + 256 * c_; \
            int l_ = id_ & 31, K_ = (id_ >> 5) & 3, R_ = id_ >> 7; \
            CP16(sb + A_OFF(st_) + id_ * 16, \
                 Xp4 + ((size_t)(Rbase + R_) * KTOT + (t) * 4 + K_) * 32 + l_); \
        } \
        _Pragma("unroll") \
        for (int c_ = 0; c_ < 8; c_++) { \
            int id_ = tid + 256 * c_; \
            int l_ = id_ & 31, K_ = (id_ >> 5) & 3, Nb_ = id_ >> 7; \
            CP16(sb + B_OFF(st_) + id_ * 16, \
                 Wp4 + ((size_t)(NbBase + Nb_) * KTOT + (t) * 4 + K_) * 32 + l_); \
        } \
    } while (0)

    G1_ISSUE(0); CP_COMMIT();
    G1_ISSUE(1); CP_COMMIT();

    for (int t = 0; t < T; t++) {
        CP_WAIT1();
        __syncthreads();
        if (t + 2 < T) G1_ISSUE(t + 2);
        CP_COMMIT();

        const int st = t % NST;
        const uint4* As = (const uint4*)(smem + A_OFF(st));
        const uint4* Bs = (const uint4*)(smem + B_OFF(st));
        #pragma unroll
        for (int kk = 0; kk < 4; kk++) {
            uint4 av[4], bv[4];
            #pragma unroll
            for (int fm = 0; fm < 4; fm++)
                av[fm] = As[((warpM * 4 + fm) * 4 + kk) * 32 + lane];
            #pragma unroll
            for (int p = 0; p < 4; p++)
                bv[p] = Bs[((warpN * 4 + p) * 4 + kk) * 32 + lane];
            #pragma unroll
            for (int fm = 0; fm < 4; fm++)
                #pragma unroll
                for (int p = 0; p < 4; p++) {
                    MMA4(acc[fm][2 * p],     av[fm], bv[p].x, bv[p].z);
                    MMA4(acc[fm][2 * p + 1], av[fm], bv[p].y, bv[p].w);
                }
        }
    }
    #undef G1_ISSUE

    // Epilogue: restage in smem, write row-major fp32 h (coalesced float4)
    __syncthreads();
    float* Hs = (float*)smem;          // stride 264 floats
    #pragma unroll
    for (int fm = 0; fm < 4; fm++) {
        int r = warpM * 64 + fm * 16 + g;
        #pragma unroll
        for (int fn = 0; fn < 8; fn++) {
            int c = warpN * 64 + fn * 8 + 2 * q;
            *(float2*)&Hs[r * 264 + c]       = *(float2*)&acc[fm][fn][0];
            *(float2*)&Hs[(r + 8) * 264 + c] = *(float2*)&acc[fm][fn][2];
        }
    }
    __syncthreads();
    #pragma unroll
    for (int p = 0; p < 32; p++) {
        int idx = tid + p * 256;
        int row = idx >> 6, col4 = idx & 63;
        float4 v = *(float4*)&Hs[row * 264 + col4 * 4];
        *(float4*)&g_h[(size_t)(rowBase + row) * DDIM + colBase + col4 * 4] = v;
    }
}

// ---------------------------------------------------------------------------
// s1/s2: one warp per row of h (row-major)
// ---------------------------------------------------------------------------
__global__ __launch_bounds__(256) void s12_kernel(const float* __restrict__ a) {
    const int wid = threadIdx.x >> 5, lane = threadIdx.x & 31;
    const int i = blockIdx.x * 8 + wid;
    const float* hr = g_h + (size_t)i * DDIM;
    float s1 = 0.f, s2 = 0.f;
    #pragma unroll 4
    for (int kb = 0; kb < 32; kb++) {
        int idx = kb * 128 + lane * 4;
        float4 h4 = *(const float4*)&hr[idx];
        float4 a1 = *(const float4*)&a[idx];
        float4 a2 = *(const float4*)&a[DDIM + idx];
        s1 += h4.x * a1.x + h4.y * a1.y + h4.z * a1.z + h4.w * a1.w;
        s2 += h4.x * a2.x + h4.y * a2.y + h4.z * a2.z + h4.w * a2.w;
    }
    #pragma unroll
    for (int s = 16; s > 0; s >>= 1) {
        s1 += __shfl_xor_sync(0xffffffffu, s1, s);
        s2 += __shfl_xor_sync(0xffffffffu, s2, s);
    }
    if (lane == 0) { g_s1[i] = s1; g_s2[i] = s2; }
}

__global__ __launch_bounds__(256) void maxs2_kernel() {
    __shared__ float sm[256];
    float m = -1e30f;
    for (int j = threadIdx.x; j < NROWS; j += 256) m = fmaxf(m, g_s2[j]);
    sm[threadIdx.x] = m;
    __syncthreads();
    for (int s = 128; s > 0; s >>= 1) {
        if (threadIdx.x < s) sm[threadIdx.x] = fmaxf(sm[threadIdx.x], sm[threadIdx.x + s]);
        __syncthreads();
    }
    if (threadIdx.x == 0) g_m2 = sm[0];
}

__global__ __launch_bounds__(256) void prep_kernel() {
    const int i = blockIdx.x * 256 + threadIdx.x;
    if (i >= NROWS) return;
    const float s1v = g_s1[i], s2v = g_s2[i], m2 = g_m2;
    const float t = s1v + m2;
    const float M = (t > 0.f) ? t : ALPHA * t;
    g_F1p[i] = expf(s1v - M);
    g_F1n[i] = expf(ALPHA * s1v - M);
    g_E2p[i] = expf(s2v);
    g_E2n[i] = expf(ALPHA * s2v);
}

// ---------------------------------------------------------------------------
// Rank (sort by s2 descending) via counting; scatter sorted arrays
// ---------------------------------------------------------------------------
__global__ __launch_bounds__(256) void rank_kernel() {
    __shared__ float tile[1024];
    const int j = blockIdx.x * 256 + threadIdx.x;
    const float v = g_s2[j];
    int cnt = 0;
    for (int c0 = 0; c0 < NROWS; c0 += 1024) {
        for (int k = threadIdx.x; k < 1024; k += 256) tile[k] = g_s2[c0 + k];
        __syncthreads();
        #pragma unroll 4
        for (int k = 0; k < 1024; k++) {
            float u = tile[k];
            cnt += (u > v) || (u == v && (c0 + k) < j);
        }
        __syncthreads();
    }
    g_sIdx[cnt] = j;
    g_sS2[cnt] = v;
    g_sWp[cnt] = g_E2p[j];
    g_sWn[cnt] = g_E2n[j];
}

// ---------------------------------------------------------------------------
// Scalar exclusive prefix sums of sWp/sWn (one block)
// ---------------------------------------------------------------------------
__global__ __launch_bounds__(256) void sscan_kernel() {
    __shared__ float pp[256], pn[256];
    const int t = threadIdx.x;
    const int base = t * 32;
    float lp = 0.f, ln = 0.f;
    for (int k = 0; k < 32; k++) { lp += g_sWp[base + k]; ln += g_sWn[base + k]; }
    pp[t] = lp; pn[t] = ln;
    __syncthreads();
    // inclusive scan (Hillis-Steele)
    for (int off = 1; off < 256; off <<= 1) {
        float vp = (t >= off) ? pp[t - off] : 0.f;
        float vn = (t >= off) ? pn[t - off] : 0.f;
        __syncthreads();
        pp[t] += vp; pn[t] += vn;
        __syncthreads();
    }
    float rp = (t > 0) ? pp[t - 1] : 0.f;
    float rn = (t > 0) ? pn[t - 1] : 0.f;
    for (int k = 0; k < 32; k++) {
        g_psP[base + k] = rp;
        g_psN[base + k] = rn;
        rp += g_sWp[base + k];
        rn += g_sWn[base + k];
    }
    if (t == 255) { g_psP[NROWS] = rp; g_psN[NROWS] = rn; }
}

// ---------------------------------------------------------------------------
// Per-row cutoff (binary search over sS2 desc) + Zinv
// ---------------------------------------------------------------------------
__global__ __launch_bounds__(256) void cut_kernel() {
    const int i = blockIdx.x * 256 + threadIdx.x;
    const float thr = -g_s1[i];
    int lo = 0, hi = NROWS;
    while (lo < hi) {
        int mid = (lo + hi) >> 1;
        if (g_sS2[mid] > thr) lo = mid + 1; else hi = mid;
    }
    const int c = lo;
    const float zp = g_psP[c];
    const float zn = g_psN[NROWS] - g_psN[c];
    const float z = g_F1p[i] * zp + g_F1n[i] * zn;
    g_cut[i] = c;
    g_zinv[i] = 1.0f / z;
}

// ---------------------------------------------------------------------------
// Chunk sums: CS[K][c] = sum over 128 sorted rows of w * h[row][c]
// ---------------------------------------------------------------------------
__global__ __launch_bounds__(256) void chunksum_kernel() {
    __shared__ float wp[CHROWS], wn[CHROWS];
    __shared__ int ridx[CHROWS];
    const int K = blockIdx.y;
    const int cb = blockIdx.x * 512;
    const int tid = threadIdx.x;
    if (tid < CHROWS) {
        wp[tid] = g_sWp[K * CHROWS + tid];
        wn[tid] = g_sWn[K * CHROWS + tid];
        ridx[tid] = g_sIdx[K * CHROWS + tid];
    }
    __syncthreads();
    const int c0 = cb + tid, c1 = cb + 256 + tid;
    float ap0 = 0.f, an0 = 0.f, ap1 = 0.f, an1 = 0.f;
    for (int r = 0; r < CHROWS; r++) {
        const float* hrow = g_h + (size_t)ridx[r] * DDIM;
        float h0 = hrow[c0], h1 = hrow[c1];
        ap0 += wp[r] * h0; an0 += wn[r] * h0;
        ap1 += wp[r] * h1; an1 += wn[r] * h1;
    }
    g_CSp[K * DDIM + c0] = ap0; g_CSn[K * DDIM + c0] = an0;
    g_CSp[K * DDIM + c1] = ap1; g_CSn[K * DDIM + c1] = an1;
}

// ---------------------------------------------------------------------------
// Chunk exclusive scan per column (64 chunks)
// ---------------------------------------------------------------------------
__global__ __launch_bounds__(256) void chunkscan_kernel() {
    const int col = blockIdx.x * 256 + threadIdx.x;
    float rp = 0.f, rn = 0.f;
    for (int K = 0; K < NCHUNK; K++) {
        g_CPp[K * DDIM + col] = rp;
        g_CPn[K * DDIM + col] = rn;
        rp += g_CSp[K * DDIM + col];
        rn += g_CSn[K * DDIM + col];
    }
    g_TOTn[col] = rn;
}

// ---------------------------------------------------------------------------
// PS fill: PS[pos][col] for pos = K*128+r+1 (exclusive prefix at each pos)
// ---------------------------------------------------------------------------
__global__ __launch_bounds__(256) void psfill_kernel() {
    __shared__ float wp[CHROWS], wn[CHROWS];
    __shared__ int ridx[CHROWS];
    const int K = blockIdx.y;
    const int cb = blockIdx.x * 512;
    const int tid = threadIdx.x;
    if (tid < CHROWS) {
        wp[tid] = g_sWp[K * CHROWS + tid];
        wn[tid] = g_sWn[K * CHROWS + tid];
        ridx[tid] = g_sIdx[K * CHROWS + tid];
    }
    __syncthreads();
    const int c0 = cb + tid, c1 = cb + 256 + tid;
    float2 r0, r1;
    r0.x = g_CPp[K * DDIM + c0]; r0.y = g_CPn[K * DDIM + c0];
    r1.x = g_CPp[K * DDIM + c1]; r1.y = g_CPn[K * DDIM + c1];
    for (int r = 0; r < CHROWS; r++) {
        const float* hrow = g_h + (size_t)ridx[r] * DDIM;
        float h0 = hrow[c0], h1 = hrow[c1];
        r0.x += wp[r] * h0; r0.y += wn[r] * h0;
        r1.x += wp[r] * h1; r1.y += wn[r] * h1;
        size_t pos = (size_t)(K * CHROWS + r + 1) * DDIM;
        g_PS[pos + c0] = r0;
        g_PS[pos + c1] = r1;
    }
}

__global__ __launch_bounds__(256) void pszero_kernel() {
    const int col = blockIdx.x * 256 + threadIdx.x;
    g_PS[col] = make_float2(0.f, 0.f);
}

// ---------------------------------------------------------------------------
// Gather: out[i][c] = zinv * (F1p*PS[c_i][c].x + F1n*(TOTn[c] - PS[c_i][c].y))
// ---------------------------------------------------------------------------
__global__ __launch_bounds__(256) void gather_kernel(float* __restrict__ out) {
    const int i = blockIdx.x;
    const int c = g_cut[i];
    const float f1p = g_F1p[i], f1n = g_F1n[i], zi = g_zinv[i];
    const float2* ps = g_PS + (size_t)c * DDIM;
    float* orow = out + (size_t)i * DDIM;
    for (int k = threadIdx.x; k < DDIM; k += 256) {
        float2 p = ps[k];
        orow[k] = (f1p * p.x + f1n * (g_TOTn[k] - p.y)) * zi;
    }
}

// ---------------------------------------------------------------------------
extern "C" void kernel_launch(void* const* d_in, const int* in_sizes, int n_in,
                              void* d_out, int out_size) {
    const float* x = nullptr;
    const float* W = nullptr;
    const float* a = nullptr;
    for (int i = 0; i < n_in; i++) {
        if (in_sizes[i] == 33554432)      x = (const float*)d_in[i];
        else if (in_sizes[i] == 16777216) W = (const float*)d_in[i];
        else if (in_sizes[i] == 8192)     a = (const float*)d_in[i];
    }
    float* out = (float*)d_out;

    static bool attr_done = false;
    if (!attr_done) {
        cudaFuncSetAttribute(gemm1_kernel, cudaFuncAttributeMaxDynamicSharedMemorySize, SMEM_MAIN);
        attr_done = true;
    }

    void* xp; cudaGetSymbolAddress(&xp, g_Xp);
    void* wp; cudaGetSymbolAddress(&wp, g_Wp);

    permute_kernel<<<dim3(8, NROWS / 16), 256>>>(x, (float4*)xp);
    permute_kernel<<<dim3(8, DDIM / 16), 256>>>(W, (float4*)wp);

    dim3 grid(DDIM / BN, NROWS / BM);   // (16, 64)
    gemm1_kernel<<<grid, 256, SMEM_MAIN>>>();

    s12_kernel<<<NROWS / 8, 256>>>(a);
    maxs2_kernel<<<1, 256>>>();
    prep_kernel<<<NROWS / 256, 256>>>();
    rank_kernel<<<NROWS / 256, 256>>>();
    sscan_kernel<<<1, 256>>>();
    cut_kernel<<<NROWS / 256, 256>>>();
    chunksum_kernel<<<dim3(DDIM / 512, NCHUNK), 256>>>();
    chunkscan_kernel<<<DDIM / 256, 256>>>();
    psfill_kernel<<<dim3(DDIM / 512, NCHUNK), 256>>>();
    pszero_kernel<<<DDIM / 256, 256>>>();
    gather_kernel<<<NROWS, 256>>>(out);
}